// round 4
// baseline (speedup 1.0000x reference)
#include <cuda_runtime.h>
#include <math.h>
#include <stdint.h>

#define B_   32
#define S_   64
#define E_   512
#define H_   1024
#define V_   32000
#define G3H  (3 * H_)
#define NTOK (B_ * S_)
#define BH   (B_ * H_)

// ---------------- scratch (device globals; no allocation allowed) ----------------
__device__ float g_ex[NTOK * E_];      // encoder embeddings  [2048, 512]
__device__ float g_dx[NTOK * E_];      // decoder embeddings  [2048, 512]
__device__ float g_xgA[NTOK * G3H];    // input gates buffer A [2048, 3072]
__device__ float g_xgB[NTOK * G3H];    // input gates buffer B [2048, 3072]
__device__ float g_seqA[NTOK * H_];    // sequence buffer
__device__ float g_seqB[NTOK * H_];    // sequence buffer
__device__ float g_h[8][BH];           // 4 layers x ping-pong hidden state [32,1024]

// ---------------- embedding gather ----------------
__global__ void embed_kernel(const int* __restrict__ idx,
                             const float* __restrict__ emb,
                             float* __restrict__ out) {
    int tok = blockIdx.x;
    int row = idx[tok];
    const float4* src = (const float4*)(emb + (size_t)row * E_);
    float4* dst = (float4*)(out + (size_t)tok * E_);
    for (int i = threadIdx.x; i < E_ / 4; i += blockDim.x) dst[i] = src[i];
}

// ---------------- fp32 SGEMM, double-buffered: C[M,N] = A[M,K]*W[N,K]^T + bias ----------------
// 128x128 tile, BK=16, 256 threads, 8x8 per thread, smem double buffer + reg prefetch.
// Requires M%128==0, N%128==0, K%16==0. Grid: (M/128, N/128) — M fastest for W reuse.
#define BM 128
#define BN 128
#define BK 16

__global__ __launch_bounds__(256)
void sgemm_db_kernel(const float* __restrict__ A,
                     const float* __restrict__ W,
                     const float* __restrict__ bias,
                     float* __restrict__ C,
                     int M, int N, int K) {
    __shared__ float As[2][BK][BM];
    __shared__ float Ws[2][BK][BN];

    const int tid = threadIdx.x;
    const int bm = blockIdx.x * BM;
    const int bn = blockIdx.y * BN;

    // loader mapping: each thread loads 2 float4 per matrix per tile
    const int lrow = tid & 127;          // row within tile
    const int kb   = (tid >> 7) * 8;     // k base: 0 or 8

    const int tx = tid & 15;             // 0..15
    const int ty = tid >> 4;             // 0..15

    const float* Ag = A + (size_t)(bm + lrow) * K + kb;
    const float* Wg = W + (size_t)(bn + lrow) * K + kb;

    float acc[8][8];
#pragma unroll
    for (int i = 0; i < 8; i++)
#pragma unroll
        for (int j = 0; j < 8; j++) acc[i][j] = 0.f;

    float4 pa0, pa1, pw0, pw1;

    // prefetch tile 0
    pa0 = *(const float4*)(Ag);
    pa1 = *(const float4*)(Ag + 4);
    pw0 = *(const float4*)(Wg);
    pw1 = *(const float4*)(Wg + 4);

    // stage tile 0 -> buf 0
    {
        As[0][kb + 0][lrow] = pa0.x; As[0][kb + 1][lrow] = pa0.y;
        As[0][kb + 2][lrow] = pa0.z; As[0][kb + 3][lrow] = pa0.w;
        As[0][kb + 4][lrow] = pa1.x; As[0][kb + 5][lrow] = pa1.y;
        As[0][kb + 6][lrow] = pa1.z; As[0][kb + 7][lrow] = pa1.w;
        Ws[0][kb + 0][lrow] = pw0.x; Ws[0][kb + 1][lrow] = pw0.y;
        Ws[0][kb + 2][lrow] = pw0.z; Ws[0][kb + 3][lrow] = pw0.w;
        Ws[0][kb + 4][lrow] = pw1.x; Ws[0][kb + 5][lrow] = pw1.y;
        Ws[0][kb + 6][lrow] = pw1.z; Ws[0][kb + 7][lrow] = pw1.w;
    }
    __syncthreads();

    int buf = 0;
    for (int k0 = BK; k0 < K; k0 += BK) {
        // issue global loads for next tile (long latency, overlapped with FFMAs below)
        pa0 = *(const float4*)(Ag + k0);
        pa1 = *(const float4*)(Ag + k0 + 4);
        pw0 = *(const float4*)(Wg + k0);
        pw1 = *(const float4*)(Wg + k0 + 4);

        // compute on current buffer
#pragma unroll
        for (int kk = 0; kk < BK; kk++) {
            float a[8], b[8];
            *(float4*)&a[0] = *(const float4*)&As[buf][kk][ty * 4];
            *(float4*)&a[4] = *(const float4*)&As[buf][kk][64 + ty * 4];
            *(float4*)&b[0] = *(const float4*)&Ws[buf][kk][tx * 4];
            *(float4*)&b[4] = *(const float4*)&Ws[buf][kk][64 + tx * 4];
#pragma unroll
            for (int i = 0; i < 8; i++)
#pragma unroll
                for (int j = 0; j < 8; j++) acc[i][j] += a[i] * b[j];
        }

        // stage next tile into alternate buffer
        const int nb = buf ^ 1;
        As[nb][kb + 0][lrow] = pa0.x; As[nb][kb + 1][lrow] = pa0.y;
        As[nb][kb + 2][lrow] = pa0.z; As[nb][kb + 3][lrow] = pa0.w;
        As[nb][kb + 4][lrow] = pa1.x; As[nb][kb + 5][lrow] = pa1.y;
        As[nb][kb + 6][lrow] = pa1.z; As[nb][kb + 7][lrow] = pa1.w;
        Ws[nb][kb + 0][lrow] = pw0.x; Ws[nb][kb + 1][lrow] = pw0.y;
        Ws[nb][kb + 2][lrow] = pw0.z; Ws[nb][kb + 3][lrow] = pw0.w;
        Ws[nb][kb + 4][lrow] = pw1.x; Ws[nb][kb + 5][lrow] = pw1.y;
        Ws[nb][kb + 6][lrow] = pw1.z; Ws[nb][kb + 7][lrow] = pw1.w;
        __syncthreads();
        buf = nb;
    }

    // last tile compute
#pragma unroll
    for (int kk = 0; kk < BK; kk++) {
        float a[8], b[8];
        *(float4*)&a[0] = *(const float4*)&As[buf][kk][ty * 4];
        *(float4*)&a[4] = *(const float4*)&As[buf][kk][64 + ty * 4];
        *(float4*)&b[0] = *(const float4*)&Ws[buf][kk][tx * 4];
        *(float4*)&b[4] = *(const float4*)&Ws[buf][kk][64 + tx * 4];
#pragma unroll
        for (int i = 0; i < 8; i++)
#pragma unroll
            for (int j = 0; j < 8; j++) acc[i][j] += a[i] * b[j];
    }

    // epilogue: bias add + vectorized stores
#pragma unroll
    for (int i = 0; i < 8; i++) {
        int m = bm + ((i < 4) ? (ty * 4 + i) : (64 + ty * 4 + (i - 4)));
#pragma unroll
        for (int half = 0; half < 2; half++) {
            int n = bn + half * 64 + tx * 4;
            float4 bv = *(const float4*)(bias + n);
            float4 o;
            o.x = acc[i][half * 4 + 0] + bv.x;
            o.y = acc[i][half * 4 + 1] + bv.y;
            o.z = acc[i][half * 4 + 2] + bv.z;
            o.w = acc[i][half * 4 + 3] + bv.w;
            *(float4*)(C + (size_t)m * N + n) = o;
        }
    }
}

// ---------------- fused GRU time step (body shared by single & dual) ----------------
__device__ __forceinline__ void gru_step_body(
        const float* __restrict__ h_prev,
        const float* __restrict__ Whh,
        const float* __restrict__ bhh,
        const float* __restrict__ xg,
        int t, int zero_init, int jblk,
        float* __restrict__ h_next,
        float* __restrict__ y,
        float* h_s /* [H_][B_] smem */) {
    const int tid = threadIdx.x;
    const int b = tid & 31;
    const int j = (jblk << 3) + (tid >> 5);

    float accr = bhh[j];
    float accz = bhh[H_ + j];
    float accn = bhh[2 * H_ + j];
    float h_old = 0.f;

    if (!zero_init) {
        for (int i4 = tid; i4 < BH / 4; i4 += 256) {
            int lin = i4 * 4;
            int bb = lin >> 10;
            int kk = lin & (H_ - 1);
            float4 v = *(const float4*)(h_prev + lin);
            h_s[(kk + 0) * B_ + bb] = v.x;
            h_s[(kk + 1) * B_ + bb] = v.y;
            h_s[(kk + 2) * B_ + bb] = v.z;
            h_s[(kk + 3) * B_ + bb] = v.w;
        }
        __syncthreads();

        const float* wr = Whh + (size_t)j * H_;
        const float* wz = Whh + (size_t)(H_ + j) * H_;
        const float* wn = Whh + (size_t)(2 * H_ + j) * H_;

#pragma unroll 8
        for (int k = 0; k < H_; k += 4) {
            float4 r4 = __ldg((const float4*)(wr + k));
            float4 z4 = __ldg((const float4*)(wz + k));
            float4 n4 = __ldg((const float4*)(wn + k));
            float h0 = h_s[(k + 0) * B_ + b];
            float h1 = h_s[(k + 1) * B_ + b];
            float h2 = h_s[(k + 2) * B_ + b];
            float h3 = h_s[(k + 3) * B_ + b];
            accr += h0 * r4.x + h1 * r4.y + h2 * r4.z + h3 * r4.w;
            accz += h0 * z4.x + h1 * z4.y + h2 * z4.z + h3 * z4.w;
            accn += h0 * n4.x + h1 * n4.y + h2 * n4.z + h3 * n4.w;
        }
        h_old = h_s[j * B_ + b];
    }

    const float* xp = xg + ((size_t)b * S_ + t) * G3H;
    float r = 1.f / (1.f + expf(-(xp[j] + accr)));
    float z = 1.f / (1.f + expf(-(xp[H_ + j] + accz)));
    float n = tanhf(xp[2 * H_ + j] + r * accn);
    float hnew = (1.f - z) * n + z * h_old;

    h_next[b * H_ + j] = hnew;
    if (y) y[((size_t)b * S_ + t) * H_ + j] = hnew;
}

__global__ __launch_bounds__(256)
void gru_step_kernel(const float* __restrict__ h_prev,
                     const float* __restrict__ Whh,
                     const float* __restrict__ bhh,
                     const float* __restrict__ xg,
                     int t, int zero_init,
                     float* __restrict__ h_next,
                     float* __restrict__ y) {
    extern __shared__ float h_s[];
    gru_step_body(h_prev, Whh, bhh, xg, t, zero_init, blockIdx.x, h_next, y, h_s);
}

// dual: blocks 0-127 run scan A, blocks 128-255 run scan B (independent layers)
__global__ __launch_bounds__(256)
void gru_step_dual_kernel(const float* hA, const float* WA, const float* bA,
                          const float* xA, int ziA, float* hnA, float* yA,
                          const float* hB, const float* WB, const float* bB,
                          const float* xB, int ziB, float* hnB, float* yB,
                          int t) {
    extern __shared__ float h_s[];
    if (blockIdx.x < 128)
        gru_step_body(hA, WA, bA, xA, t, ziA, blockIdx.x, hnA, yA, h_s);
    else
        gru_step_body(hB, WB, bB, xB, t, ziB, blockIdx.x - 128, hnB, yB, h_s);
}

// ---------------- driver ----------------
static void run_scan(const float* Whh, const float* bhh, const float* xg,
                     float* hpair, const float* h_init, int zero0, float* yout) {
    for (int t = 0; t < S_; t++) {
        const float* hin;
        int zi = 0;
        if (t == 0) {
            if (zero0) { hin = hpair; zi = 1; }
            else       { hin = h_init; }
        } else {
            hin = hpair + (t & 1) * BH;
        }
        float* hout = hpair + ((t + 1) & 1) * BH;
        gru_step_kernel<<<128, 256, 131072>>>(hin, Whh, bhh, xg, t, zi, hout, yout);
    }
}

extern "C" void kernel_launch(void* const* d_in, const int* in_sizes, int n_in,
                              void* d_out, int out_size) {
    const int*   enc_X   = (const int*)d_in[0];
    const int*   dec_X   = (const int*)d_in[1];
    const float* emb_enc = (const float*)d_in[2];
    const float* emb_dec = (const float*)d_in[3];
    const float* eW0i = (const float*)d_in[4];
    const float* eW0h = (const float*)d_in[5];
    const float* eb0i = (const float*)d_in[6];
    const float* eb0h = (const float*)d_in[7];
    const float* eW1i = (const float*)d_in[8];
    const float* eW1h = (const float*)d_in[9];
    const float* eb1i = (const float*)d_in[10];
    const float* eb1h = (const float*)d_in[11];
    const float* dW0i = (const float*)d_in[12];
    const float* dW0h = (const float*)d_in[13];
    const float* db0i = (const float*)d_in[14];
    const float* db0h = (const float*)d_in[15];
    const float* dW1i = (const float*)d_in[16];
    const float* dW1h = (const float*)d_in[17];
    const float* db1i = (const float*)d_in[18];
    const float* db1h = (const float*)d_in[19];
    const float* fcW  = (const float*)d_in[20];
    const float* fcb  = (const float*)d_in[21];
    float* out = (float*)d_out;

    float *ex, *dx, *xgA, *xgB, *seqA, *seqB, *hb;
    cudaGetSymbolAddress((void**)&ex,   g_ex);
    cudaGetSymbolAddress((void**)&dx,   g_dx);
    cudaGetSymbolAddress((void**)&xgA,  g_xgA);
    cudaGetSymbolAddress((void**)&xgB,  g_xgB);
    cudaGetSymbolAddress((void**)&seqA, g_seqA);
    cudaGetSymbolAddress((void**)&seqB, g_seqB);
    cudaGetSymbolAddress((void**)&hb,   g_h);

    cudaFuncSetAttribute(gru_step_kernel,
                         cudaFuncAttributeMaxDynamicSharedMemorySize, 131072);
    cudaFuncSetAttribute(gru_step_dual_kernel,
                         cudaFuncAttributeMaxDynamicSharedMemorySize, 131072);

    // embeddings
    embed_kernel<<<NTOK, 128>>>(enc_X, emb_enc, ex);
    embed_kernel<<<NTOK, 128>>>(dec_X, emb_dec, dx);

    dim3 g3h(NTOK / BM, G3H / BN);   // x = M tiles (fast), y = N tiles

    // encoder layer 0: xg then scan (y0 -> seqA, final h at hb pair0 buf0)
    sgemm_db_kernel<<<g3h, 256>>>(ex, eW0i, eb0i, xgA, NTOK, G3H, E_);
    run_scan(eW0h, eb0h, xgA, hb + 0 * 2 * BH, nullptr, 1, seqA);

    // enc layer 1 xg (consumes seqA) and dec layer 0 xg — both ready now
    sgemm_db_kernel<<<g3h, 256>>>(seqA, eW1i, eb1i, xgA, NTOK, G3H, H_);
    sgemm_db_kernel<<<g3h, 256>>>(dx,   dW0i, db0i, xgB, NTOK, G3H, E_);

    // dual scan: enc layer 1 (zero init, no y) || dec layer 0 (init h_enc0, y->seqA)
    {
        float* hpA = hb + 1 * 2 * BH;   // enc1 ping-pong
        float* hpB = hb + 2 * 2 * BH;   // dec0 ping-pong
        const float* h0B = hb + 0 * 2 * BH;  // enc0 final hidden
        for (int t = 0; t < S_; t++) {
            const float* hinA; int ziA = 0;
            const float* hinB; int ziB = 0;
            if (t == 0) { hinA = hpA; ziA = 1; hinB = h0B; }
            else        { hinA = hpA + (t & 1) * BH; hinB = hpB + (t & 1) * BH; }
            float* houtA = hpA + ((t + 1) & 1) * BH;
            float* houtB = hpB + ((t + 1) & 1) * BH;
            gru_step_dual_kernel<<<256, 256, 131072>>>(
                hinA, eW1h, eb1h, xgA, ziA, houtA, nullptr,
                hinB, dW0h, db0h, xgB, ziB, houtB, seqA, t);
        }
    }

    // decoder layer 1 (init = enc layer1 final hidden), y -> seqB
    sgemm_db_kernel<<<g3h, 256>>>(seqA, dW1i, db1i, xgA, NTOK, G3H, H_);
    run_scan(dW1h, db1h, xgA, hb + 3 * 2 * BH, hb + 1 * 2 * BH, 0, seqB);

    // final projection to vocab
    dim3 fc(NTOK / BM, V_ / BN);
    sgemm_db_kernel<<<fc, 256>>>(seqB, fcW, fcb, out, NTOK, V_, H_);
}